// round 17
// baseline (speedup 1.0000x reference)
#include <cuda_runtime.h>
#include <cuda_bf16.h>
#include <math.h>
#include <stdint.h>

#define FEAT      128
#define N_RELS    8
#define MAX_NODES 100000
#define BK        32
#define ASTRIDE   40            // bf16 elems per smem row (32 + 8 pad -> 80B)

// ---------------------------------------------------------------------------
// Scratch (__device__ globals: allocation-free rule)
// ---------------------------------------------------------------------------
__device__ float g_h_all[(size_t)MAX_NODES * N_RELS * FEAT];  // [n][r][f]
__device__ float g_gate [(size_t)MAX_NODES * N_RELS];
__device__ __align__(16) __nv_bfloat16 g_WT_hi[N_RELS * FEAT * FEAT]; // [r][f][d]
__device__ __align__(16) __nv_bfloat16 g_WT_lo[N_RELS * FEAT * FEAT];

// mma.sync bf16 (family-target safe; no tcgen05 anywhere)
#define MMA_BF16(d, a, b) \
    asm volatile("mma.sync.aligned.m16n8k16.row.col.f32.bf16.bf16.f32 " \
        "{%0,%1,%2,%3}, {%4,%5,%6,%7}, {%8,%9}, {%0,%1,%2,%3};" \
        : "+f"((d)[0]), "+f"((d)[1]), "+f"((d)[2]), "+f"((d)[3]) \
        : "r"((a)[0]), "r"((a)[1]), "r"((a)[2]), "r"((a)[3]), \
          "r"((b)[0]), "r"((b)[1]))

// ---------------------------------------------------------------------------
// W prep: transpose + bf16 hi/lo split.  out[r][f][d] from W[r][d][f]
// ---------------------------------------------------------------------------
__global__ void rgcn_wprep(const float* __restrict__ W) {
    int idx = blockIdx.x * blockDim.x + threadIdx.x;
    if (idx >= N_RELS * FEAT * FEAT) return;
    int d = idx & 127, f = (idx >> 7) & 127, r = idx >> 14;
    float w = W[((size_t)r * FEAT + d) * FEAT + f];
    __nv_bfloat16 hi = __float2bfloat16(w);
    float lo = w - __bfloat162float(hi);
    g_WT_hi[idx] = hi;
    g_WT_lo[idx] = __float2bfloat16(lo);
}

// ---------------------------------------------------------------------------
// Tensor GEMM (3xBF16) + fused gate GEMV:
//   h_all[m][r][f] = h[m][:] @ W[r][:][f]
//   g_gate[m][r]   = h[m][:] . gw[r][:]      (computed by the loader threads)
// CTA: 128x128 tile for one rel. 8 warps (4m x 2n), warp tile 32x64.
// ---------------------------------------------------------------------------
__global__ __launch_bounds__(256) void rgcn_gemm_mma(const float* __restrict__ h,
                                                     const __nv_bfloat16* __restrict__ WThi,
                                                     const __nv_bfloat16* __restrict__ WTlo,
                                                     const float* __restrict__ gw,
                                                     int n_nodes)
{
    __shared__ __align__(16) __nv_bfloat16 sAhi[128 * ASTRIDE];
    __shared__ __align__(16) __nv_bfloat16 sAlo[128 * ASTRIDE];
    __shared__ __align__(16) __nv_bfloat16 sBhi[128 * ASTRIDE];
    __shared__ __align__(16) __nv_bfloat16 sBlo[128 * ASTRIDE];

    const int tid  = threadIdx.x;
    const int lane = tid & 31;
    const int warp = tid >> 5;
    const int wm   = (warp & 3) * 32;   // warp m offset (4 warps along M)
    const int wn   = (warp >> 2) * 64;  // warp n offset (2 warps along N)
    const int g    = lane >> 2;         // 0..7
    const int tg   = lane & 3;          // 0..3

    const int r     = blockIdx.x;       // rel fast -> 8 CTAs share A via L2
    const int mBase = blockIdx.y * 128;

    const int ldRow = tid >> 2;         // 0..63
    const int ldCol = (tid & 3) * 8;    // 0,8,16,24

    const float* gwp = gw + r * FEAT;   // gate weight column for this rel

    float acc[2][8][4] = {};
    float gacc[2] = {0.f, 0.f};

    for (int c = 0; c < 4; c++) {
        // ---- gmem fetch (overlaps previous chunk's MMAs) ----
        float4 av[2][2];
        uint4  bh[2], bl[2];
#pragma unroll
        for (int half = 0; half < 2; half++) {
            const int row = half * 64 + ldRow;
            const int m   = mBase + row;
            av[half][0] = make_float4(0.f, 0.f, 0.f, 0.f);
            av[half][1] = make_float4(0.f, 0.f, 0.f, 0.f);
            if (m < n_nodes) {
                const float* p = h + (size_t)m * FEAT + c * BK + ldCol;
                av[half][0] = *(const float4*)p;
                av[half][1] = *(const float4*)(p + 4);
            }
            const size_t bi = ((size_t)(r * 128 + row)) * 128 + c * BK + ldCol;
            bh[half] = *(const uint4*)(WThi + bi);
            bl[half] = *(const uint4*)(WTlo + bi);
        }

        // ---- fused gate partial: dot(av, gw[r][c*32+ldCol..+7]) ----
        {
            float4 g0 = *(const float4*)(gwp + c * BK + ldCol);
            float4 g1 = *(const float4*)(gwp + c * BK + ldCol + 4);
#pragma unroll
            for (int half = 0; half < 2; half++) {
                gacc[half] += av[half][0].x * g0.x + av[half][0].y * g0.y +
                              av[half][0].z * g0.z + av[half][0].w * g0.w +
                              av[half][1].x * g1.x + av[half][1].y * g1.y +
                              av[half][1].z * g1.z + av[half][1].w * g1.w;
            }
        }

        __syncthreads();   // previous chunk's fragment reads are done

        // ---- split + stage into smem ----
#pragma unroll
        for (int half = 0; half < 2; half++) {
            const int row = half * 64 + ldRow;
            __nv_bfloat16 hi8[8], lo8[8];
            const float* fv = (const float*)&av[half][0];
#pragma unroll
            for (int i = 0; i < 8; i++) {
                float x = fv[i];
                __nv_bfloat16 hb = __float2bfloat16(x);
                hi8[i] = hb;
                lo8[i] = __float2bfloat16(x - __bfloat162float(hb));
            }
            *(uint4*)&sAhi[row * ASTRIDE + ldCol] = *(const uint4*)hi8;
            *(uint4*)&sAlo[row * ASTRIDE + ldCol] = *(const uint4*)lo8;
            *(uint4*)&sBhi[row * ASTRIDE + ldCol] = bh[half];
            *(uint4*)&sBlo[row * ASTRIDE + ldCol] = bl[half];
        }
        __syncthreads();

        // ---- MMA: 2 ksteps x 3 split-terms x (2m x 8n) ----
#pragma unroll
        for (int ks = 0; ks < 2; ks++) {
            const int kk = ks * 16 + tg * 2;
            uint32_t ahi[2][4], alo[2][4], bhi[8][2], blo[8][2];
#pragma unroll
            for (int mt = 0; mt < 2; mt++) {
                const int mr = wm + mt * 16 + g;
                ahi[mt][0] = *(const uint32_t*)&sAhi[mr * ASTRIDE + kk];
                ahi[mt][1] = *(const uint32_t*)&sAhi[(mr + 8) * ASTRIDE + kk];
                ahi[mt][2] = *(const uint32_t*)&sAhi[mr * ASTRIDE + kk + 8];
                ahi[mt][3] = *(const uint32_t*)&sAhi[(mr + 8) * ASTRIDE + kk + 8];
                alo[mt][0] = *(const uint32_t*)&sAlo[mr * ASTRIDE + kk];
                alo[mt][1] = *(const uint32_t*)&sAlo[(mr + 8) * ASTRIDE + kk];
                alo[mt][2] = *(const uint32_t*)&sAlo[mr * ASTRIDE + kk + 8];
                alo[mt][3] = *(const uint32_t*)&sAlo[(mr + 8) * ASTRIDE + kk + 8];
            }
#pragma unroll
            for (int nt = 0; nt < 8; nt++) {
                const int nr = wn + nt * 8 + g;
                bhi[nt][0] = *(const uint32_t*)&sBhi[nr * ASTRIDE + kk];
                bhi[nt][1] = *(const uint32_t*)&sBhi[nr * ASTRIDE + kk + 8];
                blo[nt][0] = *(const uint32_t*)&sBlo[nr * ASTRIDE + kk];
                blo[nt][1] = *(const uint32_t*)&sBlo[nr * ASTRIDE + kk + 8];
            }
#pragma unroll
            for (int mt = 0; mt < 2; mt++)
#pragma unroll
                for (int nt = 0; nt < 8; nt++) {
                    MMA_BF16(acc[mt][nt], ahi[mt], bhi[nt]);
                    MMA_BF16(acc[mt][nt], ahi[mt], blo[nt]);
                    MMA_BF16(acc[mt][nt], alo[mt], bhi[nt]);
                }
        }
    }

    // ---- gate write: quad-reduce (lanes differing in bits 0,1) ----
#pragma unroll
    for (int half = 0; half < 2; half++) {
        float gsum = gacc[half];
        gsum += __shfl_xor_sync(0xffffffffu, gsum, 1);
        gsum += __shfl_xor_sync(0xffffffffu, gsum, 2);
        const int m = mBase + half * 64 + ldRow;
        if ((tid & 3) == 0 && m < n_nodes)
            g_gate[(size_t)m * N_RELS + r] = gsum;
    }

    // ---- epilogue: c-frag rows (g, g+8), cols tg*2..+1 per n-tile ----
#pragma unroll
    for (int mt = 0; mt < 2; mt++) {
#pragma unroll
        for (int ro = 0; ro < 2; ro++) {
            const int m = mBase + wm + mt * 16 + g + ro * 8;
            if (m < n_nodes) {
                float* dstp = g_h_all + ((size_t)m * N_RELS + r) * FEAT;
#pragma unroll
                for (int nt = 0; nt < 8; nt++) {
                    float2 v;
                    v.x = acc[mt][nt][ro * 2 + 0];
                    v.y = acc[mt][nt][ro * 2 + 1];
                    *(float2*)(dstp + wn + nt * 8 + tg * 2) = v;
                }
            }
        }
    }
}

// ---------------------------------------------------------------------------
// Edge gather/scatter (warp per edge). One red.global.add.v4.f32 per lane.
// ---------------------------------------------------------------------------
__global__ __launch_bounds__(256) void rgcn_edge(const int* __restrict__ src,
                                                 const int* __restrict__ dst,
                                                 const int* __restrict__ rel,
                                                 const float* __restrict__ norm,
                                                 float* __restrict__ out,
                                                 int n_edges)
{
    int warp = (blockIdx.x * blockDim.x + threadIdx.x) >> 5;
    int lane = threadIdx.x & 31;
    if (warp >= n_edges) return;

    int s = src[warp], d = dst[warp], r = rel[warp];
    float gv    = g_gate[(size_t)s * N_RELS + r];
    float scale = norm[warp] / (1.0f + __expf(-gv));

    const float4* hp = (const float4*)(g_h_all + ((size_t)s * N_RELS + r) * FEAT);
    float4 v = hp[lane];

    float* o = out + (size_t)d * FEAT + lane * 4;   // 16B aligned
    asm volatile("red.global.add.v4.f32 [%0], {%1, %2, %3, %4};"
                 :: "l"(o), "f"(v.x * scale), "f"(v.y * scale),
                    "f"(v.z * scale), "f"(v.w * scale)
                 : "memory");
}

__global__ void rgcn_relu(float4* out, int n4)
{
    int i = blockIdx.x * blockDim.x + threadIdx.x;
    if (i < n4) {
        float4 v = out[i];
        v.x = fmaxf(v.x, 0.f); v.y = fmaxf(v.y, 0.f);
        v.z = fmaxf(v.z, 0.f); v.w = fmaxf(v.w, 0.f);
        out[i] = v;
    }
}

extern "C" void kernel_launch(void* const* d_in, const int* in_sizes, int n_in,
                              void* d_out, int out_size)
{
    const float* h    = (const float*)d_in[0];
    const float* W    = (const float*)d_in[1];
    const float* gw   = (const float*)d_in[2];
    const float* norm = (const float*)d_in[3];
    const int*   src  = (const int*)  d_in[4];
    const int*   dst  = (const int*)  d_in[5];
    const int*   rel  = (const int*)  d_in[6];
    float* out = (float*)d_out;

    const int n_nodes = in_sizes[0] / FEAT;
    const int n_edges = in_sizes[4];

    cudaMemsetAsync(out, 0, (size_t)out_size * sizeof(float));

    rgcn_wprep<<<(N_RELS * FEAT * FEAT + 255) / 256, 256>>>(W);

    __nv_bfloat16 *wthi_p = nullptr, *wtlo_p = nullptr;
    cudaGetSymbolAddress((void**)&wthi_p, g_WT_hi);
    cudaGetSymbolAddress((void**)&wtlo_p, g_WT_lo);

    dim3 ggrid(N_RELS, (n_nodes + 127) / 128);
    rgcn_gemm_mma<<<ggrid, 256>>>(h, wthi_p, wtlo_p, gw, n_nodes);

    rgcn_edge<<<((size_t)n_edges * 32 + 255) / 256, 256>>>(src, dst, rel, norm, out, n_edges);

    int n4 = out_size / 4;
    rgcn_relu<<<(n4 + 255) / 256, 256>>>((float4*)out, n4);
}